// round 1
// baseline (speedup 1.0000x reference)
#include <cuda_runtime.h>
#include <math.h>

// Problem constants (fixed by the dataset)
#define NN 100000      // nodes
#define NE 1600000     // edges
#define FIN 394        // input features
#define FH  256        // hidden features
#define FO  64         // output features

// ---------------- scratch (device globals; no allocation allowed) ----------
__device__ float  g_deg [NN];
__device__ float  g_dinv[NN];
__device__ float  g_norm[NE];
__device__ float4 g_xw1 [(size_t)NN * (FH / 4)];   // x @ W1
__device__ float4 g_agg1[(size_t)NN * (FH / 4)];   // layer-1 aggregate, then h (in place)
__device__ float4 g_hw2 [(size_t)NN * (FO / 4)];   // h @ W2

// ---------------- helpers ---------------------------------------------------
__device__ __forceinline__ void red_add_v4(float* addr, float4 v) {
    asm volatile("red.global.add.v4.f32 [%0], {%1,%2,%3,%4};"
                 :: "l"(addr), "f"(v.x), "f"(v.y), "f"(v.z), "f"(v.w)
                 : "memory");
}

// ---------------- init: zero accumulators, deg = 1 (self loop) --------------
__global__ void init_kernel(float4* out4) {
    size_t i = (size_t)blockIdx.x * blockDim.x + threadIdx.x;
    size_t stride = (size_t)gridDim.x * blockDim.x;
    float4 z = make_float4(0.f, 0.f, 0.f, 0.f);
    const size_t na = (size_t)NN * (FH / 4);
    for (size_t k = i; k < na; k += stride) g_agg1[k] = z;
    const size_t no = (size_t)NN * (FO / 4);
    for (size_t k = i; k < no; k += stride) out4[k] = z;
    for (size_t k = i; k < NN; k += stride) g_deg[k] = 1.0f;
}

// ---------------- degree over destinations ----------------------------------
__global__ void deg_kernel(const int* __restrict__ ei, const float* __restrict__ ew) {
    int e = blockIdx.x * blockDim.x + threadIdx.x;
    if (e < NE) atomicAdd(&g_deg[ei[NE + e]], ew[e]);
}

__global__ void dinv_kernel() {
    int i = blockIdx.x * blockDim.x + threadIdx.x;
    if (i < NN) {
        float d = g_deg[i];
        g_dinv[i] = (d > 0.f) ? rsqrtf(d) : 0.f;
    }
}

__global__ void norm_kernel(const int* __restrict__ ei, const float* __restrict__ ew) {
    int e = blockIdx.x * blockDim.x + threadIdx.x;
    if (e < NE) g_norm[e] = g_dinv[ei[e]] * ew[e] * g_dinv[ei[NE + e]];
}

// ---------------- SIMT fp32 GEMM: C[M,N] = A[M,K] @ B[K,N] ------------------
template <int BM, int BN, int BK, int TM, int TN>
__global__ void gemm_kernel(const float* __restrict__ A, const float* __restrict__ B,
                            float* __restrict__ C, int M, int N, int K) {
    constexpr int THREADS = (BM / TM) * (BN / TN);
    __shared__ float As[BK][BM];
    __shared__ float Bs[BK][BN];

    const int tid = threadIdx.x;
    const int tx = tid % (BN / TN);
    const int ty = tid / (BN / TN);
    const int row0 = blockIdx.y * BM;
    const int col0 = blockIdx.x * BN;

    float acc[TM][TN];
#pragma unroll
    for (int i = 0; i < TM; i++)
#pragma unroll
        for (int j = 0; j < TN; j++) acc[i][j] = 0.f;

    for (int k0 = 0; k0 < K; k0 += BK) {
        // A tile: BM x BK, store transposed As[k][m]
#pragma unroll
        for (int i = tid; i < BM * BK; i += THREADS) {
            int m = i / BK, kk = i % BK;
            int gm = row0 + m, gk = k0 + kk;
            As[kk][m] = (gm < M && gk < K) ? A[(size_t)gm * K + gk] : 0.f;
        }
        // B tile: BK x BN
#pragma unroll
        for (int i = tid; i < BK * BN; i += THREADS) {
            int kk = i / BN, n = i % BN;
            int gk = k0 + kk;
            Bs[kk][n] = (gk < K) ? B[(size_t)gk * N + col0 + n] : 0.f;
        }
        __syncthreads();
#pragma unroll
        for (int kk = 0; kk < BK; kk++) {
            float ar[TM], br[TN];
#pragma unroll
            for (int i = 0; i < TM; i++) ar[i] = As[kk][ty * TM + i];
#pragma unroll
            for (int j = 0; j < TN; j++) br[j] = Bs[kk][tx * TN + j];
#pragma unroll
            for (int i = 0; i < TM; i++)
#pragma unroll
                for (int j = 0; j < TN; j++) acc[i][j] = fmaf(ar[i], br[j], acc[i][j]);
        }
        __syncthreads();
    }
#pragma unroll
    for (int i = 0; i < TM; i++) {
        int gm = row0 + ty * TM + i;
        if (gm < M) {
#pragma unroll
            for (int j = 0; j < TN; j++)
                C[(size_t)gm * N + col0 + tx * TN + j] = acc[i][j];
        }
    }
}

// ---------------- layer-1 scatter-add: agg1[dst] += norm * xw1[src] ---------
// 64 threads per edge, one float4 each (256 feats)
__global__ void agg1_kernel(const int* __restrict__ ei) {
    int t = blockIdx.x * blockDim.x + threadIdx.x;
    int e = t >> 6;
    if (e >= NE) return;
    int f = t & 63;
    int src = ei[e];
    int dst = ei[NE + e];
    float nrm = g_norm[e];
    float4 v = g_xw1[(size_t)src * (FH / 4) + f];
    v.x *= nrm; v.y *= nrm; v.z *= nrm; v.w *= nrm;
    red_add_v4((float*)&g_agg1[(size_t)dst * (FH / 4) + f], v);
}

// ---------------- h = relu(agg1 + dinv^2 * xw1 + b1)  (in place) ------------
__global__ void h_kernel(const float4* __restrict__ b1) {
    size_t idx = (size_t)blockIdx.x * blockDim.x + threadIdx.x;
    if (idx >= (size_t)NN * (FH / 4)) return;
    int i = (int)(idx >> 6);            // FH/4 = 64 float4 per row
    int f = (int)(idx & 63);
    float di = g_dinv[i];
    float s = di * di;
    float4 a = g_agg1[idx];
    float4 xw = g_xw1[idx];
    float4 b = b1[f];
    float4 r;
    r.x = fmaxf(fmaf(s, xw.x, a.x) + b.x, 0.f);
    r.y = fmaxf(fmaf(s, xw.y, a.y) + b.y, 0.f);
    r.z = fmaxf(fmaf(s, xw.z, a.z) + b.z, 0.f);
    r.w = fmaxf(fmaf(s, xw.w, a.w) + b.w, 0.f);
    g_agg1[idx] = r;
}

// ---------------- layer-2 scatter-add into d_out ----------------------------
// 16 threads per edge, one float4 each (64 feats)
__global__ void agg2_kernel(const int* __restrict__ ei, float* __restrict__ out) {
    int t = blockIdx.x * blockDim.x + threadIdx.x;
    int e = t >> 4;
    if (e >= NE) return;
    int f = t & 15;
    int src = ei[e];
    int dst = ei[NE + e];
    float nrm = g_norm[e];
    float4 v = g_hw2[(size_t)src * (FO / 4) + f];
    v.x *= nrm; v.y *= nrm; v.z *= nrm; v.w *= nrm;
    red_add_v4(out + (size_t)dst * FO + f * 4, v);
}

// ---------------- out += dinv^2 * hw2 + b2 ----------------------------------
__global__ void out_kernel(float4* __restrict__ out4, const float4* __restrict__ b2) {
    size_t idx = (size_t)blockIdx.x * blockDim.x + threadIdx.x;
    if (idx >= (size_t)NN * (FO / 4)) return;
    int i = (int)(idx >> 4);            // FO/4 = 16 float4 per row
    int f = (int)(idx & 15);
    float di = g_dinv[i];
    float s = di * di;
    float4 a = out4[idx];
    float4 hw = g_hw2[idx];
    float4 b = b2[f];
    float4 r;
    r.x = fmaf(s, hw.x, a.x) + b.x;
    r.y = fmaf(s, hw.y, a.y) + b.y;
    r.z = fmaf(s, hw.z, a.z) + b.z;
    r.w = fmaf(s, hw.w, a.w) + b.w;
    out4[idx] = r;
}

// ---------------- launch -----------------------------------------------------
extern "C" void kernel_launch(void* const* d_in, const int* in_sizes, int n_in,
                              void* d_out, int out_size) {
    const float* x  = (const float*)d_in[0];
    const int*   ei = (const int*)  d_in[1];
    const float* ew = (const float*)d_in[2];
    const float* W1 = (const float*)d_in[3];
    const float* b1 = (const float*)d_in[4];
    const float* W2 = (const float*)d_in[5];
    const float* b2 = (const float*)d_in[6];
    float* out = (float*)d_out;

    void *p_xw1, *p_agg1, *p_hw2;
    cudaGetSymbolAddress(&p_xw1, g_xw1);
    cudaGetSymbolAddress(&p_agg1, g_agg1);
    cudaGetSymbolAddress(&p_hw2, g_hw2);

    // 1. init accumulators / degree
    init_kernel<<<4096, 256>>>((float4*)d_out);
    // 2. degree + normalization coefficients
    deg_kernel<<<(NE + 255) / 256, 256>>>(ei, ew);
    dinv_kernel<<<(NN + 255) / 256, 256>>>();
    norm_kernel<<<(NE + 255) / 256, 256>>>(ei, ew);
    // 3. GEMM1: xw1 = x @ W1   (M=NN, N=FH, K=FIN)
    {
        dim3 grid(FH / 128, (NN + 127) / 128);
        gemm_kernel<128, 128, 8, 8, 8><<<grid, 256>>>(x, W1, (float*)p_xw1, NN, FH, FIN);
    }
    // 4. layer-1 aggregation (scatter-add)
    agg1_kernel<<<(int)(((size_t)NE * 64 + 255) / 256), 256>>>(ei);
    // 5. h = relu(agg1 + self + b1), in place
    h_kernel<<<(int)(((size_t)NN * (FH / 4) + 255) / 256), 256>>>((const float4*)b1);
    // 6. GEMM2: hw2 = h @ W2   (M=NN, N=FO, K=FH)
    {
        dim3 grid(FO / 64, (NN + 127) / 128);
        gemm_kernel<128, 64, 8, 8, 4><<<grid, 256>>>((const float*)p_agg1, W2, (float*)p_hw2, NN, FO, FH);
    }
    // 7. layer-2 aggregation into out
    agg2_kernel<<<(int)(((size_t)NE * 16 + 255) / 256), 256>>>(ei, out);
    // 8. out += self + b2
    out_kernel<<<(int)(((size_t)NN * (FO / 4) + 255) / 256), 256>>>((float4*)d_out, (const float4*)b2);

    (void)in_sizes; (void)n_in; (void)out_size;
}

// round 3
// speedup vs baseline: 1.4646x; 1.4646x over previous
#include <cuda_runtime.h>
#include <mma.h>
#include <math.h>

using namespace nvcuda;

// Problem constants (fixed by the dataset)
#define NN 100000      // nodes
#define NPAD 100096    // NN rounded to 128 (GEMM tile store padding)
#define NE 1600000     // edges
#define FIN 394        // input features
#define FH  256        // hidden features
#define FO  64         // output features
#define NSCAN_BLKS ((NN + 1023) / 1024)

// ---------------- scratch (device globals; no allocation allowed) ----------
__device__ float  g_deg [NN];
__device__ float  g_dinv[NN];
__device__ float  g_norm[NE];
__device__ int    g_cnt [NN];
__device__ int    g_rowptr[NN + 1];
__device__ int    g_bsum[NSCAN_BLKS];
__device__ int    g_perm[NE];
__device__ int    g_esrc[NE];
__device__ float  g_enorm[NE];
__device__ float4 g_xw1[(size_t)NPAD * (FH / 4)];   // x @ W1
__device__ float4 g_h  [(size_t)NPAD * (FH / 4)];   // relu(agg1 + self + b1)
__device__ float4 g_hw2[(size_t)NPAD * (FO / 4)];   // h @ W2

// ---------------- small prep kernels ----------------------------------------
__global__ void z1_kernel() {
    int i = blockIdx.x * blockDim.x + threadIdx.x;
    if (i < NN) { g_cnt[i] = 0; g_deg[i] = 1.0f; }   // deg starts at 1 (self loop)
}

__global__ void hist_kernel(const int* __restrict__ ei, const float* __restrict__ ew) {
    int e = blockIdx.x * blockDim.x + threadIdx.x;
    if (e < NE) {
        int dst = ei[NE + e];
        atomicAdd(&g_cnt[dst], 1);
        atomicAdd(&g_deg[dst], ew[e]);
    }
}

__global__ void dinv_kernel() {
    int i = blockIdx.x * blockDim.x + threadIdx.x;
    if (i < NN) {
        float d = g_deg[i];
        g_dinv[i] = (d > 0.f) ? rsqrtf(d) : 0.f;
    }
}

__global__ void norm_kernel(const int* __restrict__ ei, const float* __restrict__ ew) {
    int e = blockIdx.x * blockDim.x + threadIdx.x;
    if (e < NE) g_norm[e] = g_dinv[ei[e]] * ew[e] * g_dinv[ei[NE + e]];
}

// ---------------- prefix scan over g_cnt -> g_rowptr ------------------------
__global__ void scan1_kernel() {
    __shared__ int s[1024];
    int tid = threadIdx.x;
    int gi = blockIdx.x * 1024 + tid;
    int v = (gi < NN) ? g_cnt[gi] : 0;
    s[tid] = v;
    __syncthreads();
#pragma unroll
    for (int off = 1; off < 1024; off <<= 1) {
        int t = (tid >= off) ? s[tid - off] : 0;
        __syncthreads();
        s[tid] += t;
        __syncthreads();
    }
    if (gi < NN) g_rowptr[gi] = s[tid] - v;          // exclusive within block
    if (tid == 1023) g_bsum[blockIdx.x] = s[1023];
}

__global__ void scan2_kernel() {
    __shared__ int s[128];
    int tid = threadIdx.x;
    int v = (tid < NSCAN_BLKS) ? g_bsum[tid] : 0;
    s[tid] = v;
    __syncthreads();
#pragma unroll
    for (int off = 1; off < 128; off <<= 1) {
        int t = (tid >= off) ? s[tid - off] : 0;
        __syncthreads();
        s[tid] += t;
        __syncthreads();
    }
    if (tid < NSCAN_BLKS) g_bsum[tid] = s[tid] - v;  // exclusive block offsets
}

__global__ void scan3_kernel() {
    int gi = blockIdx.x * 1024 + threadIdx.x;
    if (gi < NN) {
        g_rowptr[gi] += g_bsum[blockIdx.x];
        g_cnt[gi] = 0;                               // reuse as scatter cursor
    }
    if (gi == 0) g_rowptr[NN] = NE;
}

__global__ void scatter_kernel(const int* __restrict__ ei) {
    int e = blockIdx.x * blockDim.x + threadIdx.x;
    if (e < NE) {
        int dst = ei[NE + e];
        int p = g_rowptr[dst] + atomicAdd(&g_cnt[dst], 1);
        g_perm[p] = e;
    }
}

// pre-gather (src, norm) in perm order so the agg loops read sequentially
__global__ void epk_kernel(const int* __restrict__ ei) {
    int j = blockIdx.x * blockDim.x + threadIdx.x;
    if (j < NE) {
        int e = g_perm[j];
        g_esrc[j]  = ei[e];
        g_enorm[j] = g_norm[e];
    }
}

// ---------------- 3xTF32 tensor-core GEMM: C[M,N] = A[M,K] @ B[K,N] ---------
// BM x BN block tile, BK=16, warp tile 32x32 (2x2 wmma 16x16x8 fragments).
template <int BM, int BN>
__global__ void __launch_bounds__((BM / 32) * (BN / 32) * 32, 1)
gemm_tf32_kernel(const float* __restrict__ A, const float* __restrict__ B,
                 float* __restrict__ C, int M, int N, int K) {
    constexpr int WMR = BM / 32;
    constexpr int WNR = BN / 32;
    constexpr int THREADS = WMR * WNR * 32;
    constexpr int AK = 20;          // 16 + pad
    constexpr int BNP = BN + 8;

    __shared__ float sAh[BM][AK], sAl[BM][AK];
    __shared__ float sBh[16][BNP], sBl[16][BNP];

    const int tid = threadIdx.x;
    const int wid = tid / 32;
    const int wm = wid / WNR;
    const int wn = wid % WNR;
    const int row0 = blockIdx.y * BM;
    const int col0 = blockIdx.x * BN;

    wmma::fragment<wmma::accumulator, 16, 16, 8, float> c[2][2];
#pragma unroll
    for (int i = 0; i < 2; i++)
#pragma unroll
        for (int j = 0; j < 2; j++) wmma::fill_fragment(c[i][j], 0.0f);

    for (int k0 = 0; k0 < K; k0 += 16) {
        // A tile BM x 16, split hi/lo
#pragma unroll
        for (int i = tid; i < BM * 16; i += THREADS) {
            int m = i / 16, kk = i % 16;
            int gm = row0 + m, gk = k0 + kk;
            float v = (gm < M && gk < K) ? A[(size_t)gm * K + gk] : 0.f;
            float hi = wmma::__float_to_tf32(v);
            sAh[m][kk] = hi;
            sAl[m][kk] = wmma::__float_to_tf32(v - hi);
        }
        // B tile 16 x BN, split hi/lo
#pragma unroll
        for (int i = tid; i < 16 * BN; i += THREADS) {
            int kk = i / BN, n = i % BN;
            int gk = k0 + kk;
            float v = (gk < K) ? B[(size_t)gk * N + col0 + n] : 0.f;
            float hi = wmma::__float_to_tf32(v);
            sBh[kk][n] = hi;
            sBl[kk][n] = wmma::__float_to_tf32(v - hi);
        }
        __syncthreads();

#pragma unroll
        for (int kk = 0; kk < 16; kk += 8) {
            wmma::fragment<wmma::matrix_a, 16, 16, 8, wmma::precision::tf32, wmma::row_major> ah[2], al[2];
            wmma::fragment<wmma::matrix_b, 16, 16, 8, wmma::precision::tf32, wmma::row_major> bh[2], bl[2];
#pragma unroll
            for (int i = 0; i < 2; i++) {
                wmma::load_matrix_sync(ah[i], &sAh[wm * 32 + i * 16][kk], AK);
                wmma::load_matrix_sync(al[i], &sAl[wm * 32 + i * 16][kk], AK);
            }
#pragma unroll
            for (int j = 0; j < 2; j++) {
                wmma::load_matrix_sync(bh[j], &sBh[kk][wn * 32 + j * 16], BNP);
                wmma::load_matrix_sync(bl[j], &sBl[kk][wn * 32 + j * 16], BNP);
            }
#pragma unroll
            for (int i = 0; i < 2; i++)
#pragma unroll
                for (int j = 0; j < 2; j++) {
                    wmma::mma_sync(c[i][j], ah[i], bh[j], c[i][j]);
                    wmma::mma_sync(c[i][j], ah[i], bl[j], c[i][j]);
                    wmma::mma_sync(c[i][j], al[i], bh[j], c[i][j]);
                }
        }
        __syncthreads();
    }

    // store (C is padded to NPAD rows, no row guard needed)
#pragma unroll
    for (int i = 0; i < 2; i++)
#pragma unroll
        for (int j = 0; j < 2; j++) {
            float* cp = C + (size_t)(row0 + wm * 32 + i * 16) * N + col0 + wn * 32 + j * 16;
            wmma::store_matrix_sync(cp, c[i][j], N, wmma::mem_row_major);
        }
}

// ---------------- layer-1 gather-aggregate, fused self-loop + bias + relu ---
// blockDim = (64, 4): 64 threads over FH/4 float4 columns, 4 dsts per block
__global__ void agg1_kernel(const float4* __restrict__ b1) {
    int d = blockIdx.x * 4 + threadIdx.y;
    if (d >= NN) return;
    int f = threadIdx.x;
    float di = g_dinv[d];
    float s = di * di;
    float4 xs = g_xw1[(size_t)d * 64 + f];
    float4 acc = make_float4(s * xs.x, s * xs.y, s * xs.z, s * xs.w);
    int beg = g_rowptr[d], end = g_rowptr[d + 1];
    for (int j = beg; j < end; j++) {
        int src = g_esrc[j];
        float nrm = g_enorm[j];
        float4 v = g_xw1[(size_t)src * 64 + f];
        acc.x = fmaf(nrm, v.x, acc.x);
        acc.y = fmaf(nrm, v.y, acc.y);
        acc.z = fmaf(nrm, v.z, acc.z);
        acc.w = fmaf(nrm, v.w, acc.w);
    }
    float4 b = b1[f];
    float4 r;
    r.x = fmaxf(acc.x + b.x, 0.f);
    r.y = fmaxf(acc.y + b.y, 0.f);
    r.z = fmaxf(acc.z + b.z, 0.f);
    r.w = fmaxf(acc.w + b.w, 0.f);
    g_h[(size_t)d * 64 + f] = r;
}

// ---------------- layer-2 gather-aggregate, fused self-loop + bias ----------
// blockDim = (16, 16): 16 threads over FO/4 float4 columns, 16 dsts per block
__global__ void agg2_kernel(const float4* __restrict__ b2, float4* __restrict__ out) {
    int d = blockIdx.x * 16 + threadIdx.y;
    if (d >= NN) return;
    int f = threadIdx.x;
    float di = g_dinv[d];
    float s = di * di;
    float4 hs = g_hw2[(size_t)d * 16 + f];
    float4 acc = make_float4(s * hs.x, s * hs.y, s * hs.z, s * hs.w);
    int beg = g_rowptr[d], end = g_rowptr[d + 1];
    for (int j = beg; j < end; j++) {
        int src = g_esrc[j];
        float nrm = g_enorm[j];
        float4 v = g_hw2[(size_t)src * 16 + f];
        acc.x = fmaf(nrm, v.x, acc.x);
        acc.y = fmaf(nrm, v.y, acc.y);
        acc.z = fmaf(nrm, v.z, acc.z);
        acc.w = fmaf(nrm, v.w, acc.w);
    }
    float4 b = b2[f];
    acc.x += b.x; acc.y += b.y; acc.z += b.z; acc.w += b.w;
    out[(size_t)d * 16 + f] = acc;
}

// ---------------- launch -----------------------------------------------------
extern "C" void kernel_launch(void* const* d_in, const int* in_sizes, int n_in,
                              void* d_out, int out_size) {
    const float* x  = (const float*)d_in[0];
    const int*   ei = (const int*)  d_in[1];
    const float* ew = (const float*)d_in[2];
    const float* W1 = (const float*)d_in[3];
    const float* b1 = (const float*)d_in[4];
    const float* W2 = (const float*)d_in[5];
    const float* b2 = (const float*)d_in[6];

    void *p_xw1, *p_h, *p_hw2;
    cudaGetSymbolAddress(&p_xw1, g_xw1);
    cudaGetSymbolAddress(&p_h,   g_h);
    cudaGetSymbolAddress(&p_hw2, g_hw2);

    // --- CSR build + normalization ---
    z1_kernel  <<<(NN + 255) / 256, 256>>>();
    hist_kernel<<<(NE + 255) / 256, 256>>>(ei, ew);
    dinv_kernel<<<(NN + 255) / 256, 256>>>();
    norm_kernel<<<(NE + 255) / 256, 256>>>(ei, ew);
    scan1_kernel<<<NSCAN_BLKS, 1024>>>();
    scan2_kernel<<<1, 128>>>();
    scan3_kernel<<<NSCAN_BLKS, 1024>>>();
    scatter_kernel<<<(NE + 255) / 256, 256>>>(ei);
    epk_kernel <<<(NE + 255) / 256, 256>>>(ei);

    // --- GEMM1: xw1 = x @ W1  (M=NN, N=FH=256, K=FIN=394) ---
    {
        dim3 grid(FH / 128, NPAD / 128);
        gemm_tf32_kernel<128, 128><<<grid, 512>>>(x, W1, (float*)p_xw1, NN, FH, FIN);
    }
    // --- layer-1 aggregate + relu ---
    {
        dim3 blk(64, 4);
        agg1_kernel<<<(NN + 3) / 4, blk>>>((const float4*)b1);
    }
    // --- GEMM2: hw2 = h @ W2  (M=NN, N=FO=64, K=FH=256) ---
    {
        dim3 grid(FO / 64, NPAD / 128);
        gemm_tf32_kernel<128, 64><<<grid, 256>>>((const float*)p_h, W2, (float*)p_hw2, NN, FO, FH);
    }
    // --- layer-2 aggregate -> out ---
    {
        dim3 blk(16, 16);
        agg2_kernel<<<(NN + 15) / 16, blk>>>((const float4*)b2, (float4*)d_out);
    }

    (void)in_sizes; (void)n_in; (void)out_size;
}